// round 1
// baseline (speedup 1.0000x reference)
#include <cuda_runtime.h>
#include <math.h>

#define B_       8
#define N_       1024
#define NCTA     18            // CTAs per batch
#define GRID_    (B_ * NCTA)   // 144 <= 148 SMs -> all co-resident at 1 CTA/SM
#define ROWS_MAX 57            // ceil(1024/18)
#define ROWS_SM  55            // rows held in shared memory (55*4KB = 225,280 B)
#define ITERS    100
#define RINV     (1.0f / 1024.0f)
#define LMB      10.0f

// Ping-pong partial buffers for w = K^T u  (2 * 8 * 18 * 1024 * 4 B = 576 KB)
__device__ float        g_part[2][B_][NCTA][N_];
// Monotonic per-batch barrier counters (reset by init kernel each launch)
__device__ unsigned int g_bar[B_];

__global__ void rt_init() {
    if (threadIdx.x < B_) g_bar[threadIdx.x] = 0u;
}

__device__ __forceinline__ float wred(float x) {
    x += __shfl_xor_sync(0xffffffffu, x, 16);
    x += __shfl_xor_sync(0xffffffffu, x, 8);
    x += __shfl_xor_sync(0xffffffffu, x, 4);
    x += __shfl_xor_sync(0xffffffffu, x, 2);
    x += __shfl_xor_sync(0xffffffffu, x, 1);
    return x;
}

__global__ void __launch_bounds__(1024, 1)
rt_kernel(const float* __restrict__ Mn, float* __restrict__ out) {
    extern __shared__ float sm[];
    float* Ks    = sm;                    // [ROWS_SM * N_]
    float* z_s   = sm + ROWS_SM * N_;     // [N_]
    float* u_s   = z_s + N_;              // [64]
    float* red_s = u_s + 64;              // [64]

    const int tid  = threadIdx.x;
    const int lane = tid & 31;
    const int warp = tid >> 5;
    const int b    = blockIdx.x / NCTA;
    const int pid  = blockIdx.x % NCTA;
    const int row0 = pid * ROWS_MAX;
    const int nrows = min(ROWS_MAX, N_ - row0);  // 57, except last CTA: 55
    const int nreg  = nrows - ROWS_SM;           // 2 or 0

    const float* Mb = Mn + (size_t)b * N_ * N_;

    // ---- Build K = exp(-lambda * min(M, 5)) : 55 rows in SMEM, 2 in regs ----
    float kr0 = 0.f, kr1 = 0.f;
    for (int li = 0; li < nrows; li++) {
        float m = Mb[(size_t)(row0 + li) * N_ + tid];
        float k = expf(-LMB * fminf(m, 5.0f));
        if (li < ROWS_SM)       Ks[li * N_ + tid] = k;
        else if (li == ROWS_SM) kr0 = k;
        else                    kr1 = k;
    }
    if (tid < 64) u_s[tid] = RINV;   // u0 = r (extras harmless; kr* = 0 for last CTA)
    __syncthreads();

    unsigned int gen = 0;
    float v = 0.f;

    for (int iter = 0; iter <= ITERS; iter++) {
        // ---- Pass A: w[j] = sum_i K[i][j] * u[i]  (column-parallel) ----
        float w = 0.f;
        #pragma unroll 11
        for (int li = 0; li < ROWS_SM; li++)
            w += Ks[li * N_ + tid] * u_s[li];
        w += kr0 * u_s[ROWS_SM] + kr1 * u_s[ROWS_SM + 1];

        const int buf = iter & 1;
        __stcg(&g_part[buf][b][pid][tid], w);

        // ---- Per-batch barrier (release -> arrive -> spin -> acquire) ----
        gen++;
        __syncthreads();
        if (tid == 0) {
            __threadfence();
            atomicAdd(&g_bar[b], 1u);
            const unsigned int tgt = gen * NCTA;
            volatile unsigned int* bp = &g_bar[b];
            while (*bp < tgt) { __nanosleep(40); }
            __threadfence();
        }
        __syncthreads();

        // ---- Reduce partials, z = c / w ----
        float a = 0.f;
        #pragma unroll
        for (int q = 0; q < NCTA; q++)
            a += __ldcg(&g_part[buf][b][q][tid]);
        const float z = RINV / a;
        z_s[tid] = z;
        __syncthreads();

        if (iter == ITERS) { v = z; break; }   // final pass-A gave v = c/(K^T u)

        // ---- Pass B: t[i] = sum_j K[i][j] z[j]; u[i] = r / t[i] ----
        if (warp < 14) {
            const int rb = warp << 2;
            const int r0 = rb;
            const int r1 = min(rb + 1, ROWS_SM - 1);
            const int r2 = min(rb + 2, ROWS_SM - 1);
            const int r3 = min(rb + 3, ROWS_SM - 1);
            float t0 = 0.f, t1 = 0.f, t2 = 0.f, t3 = 0.f;
            #pragma unroll 4
            for (int k = 0; k < 32; k++) {
                const int c = lane + (k << 5);
                const float zv = z_s[c];
                t0 += Ks[r0 * N_ + c] * zv;
                t1 += Ks[r1 * N_ + c] * zv;
                t2 += Ks[r2 * N_ + c] * zv;
                t3 += Ks[r3 * N_ + c] * zv;
            }
            t0 = wred(t0); t1 = wred(t1); t2 = wred(t2); t3 = wred(t3);
            if (lane == 0) {
                u_s[r0] = RINV / t0;
                if (rb + 1 < ROWS_SM) u_s[rb + 1] = RINV / t1;
                if (rb + 2 < ROWS_SM) u_s[rb + 2] = RINV / t2;
                if (rb + 3 < ROWS_SM) u_s[rb + 3] = RINV / t3;
            }
        }
        // Register-resident overflow rows (rows 55,56 of this CTA): block reduce
        float p0 = wred(kr0 * z);
        float p1 = wred(kr1 * z);
        if (lane == 0) { red_s[warp] = p0; red_s[32 + warp] = p1; }
        __syncthreads();
        if (warp == 0) {
            float s0 = wred(red_s[lane]);
            float s1 = wred(red_s[32 + lane]);
            if (lane == 0 && nreg > 0) {
                u_s[ROWS_SM]     = RINV / s0;
                u_s[ROWS_SM + 1] = RINV / s1;
            }
        }
        __syncthreads();   // u_s ready for next pass A
    }

    // ---- Write P[i][j] = u[i] * K[i][j] * v[j] ----
    float* outb = out + (size_t)b * N_ * N_;
    for (int li = 0; li < ROWS_SM; li++) {
        outb[(size_t)(row0 + li) * N_ + tid] = u_s[li] * Ks[li * N_ + tid] * v;
    }
    if (nreg > 0) {
        outb[(size_t)(row0 + ROWS_SM)     * N_ + tid] = u_s[ROWS_SM]     * kr0 * v;
        outb[(size_t)(row0 + ROWS_SM + 1) * N_ + tid] = u_s[ROWS_SM + 1] * kr1 * v;
    }
}

extern "C" void kernel_launch(void* const* d_in, const int* in_sizes, int n_in,
                              void* d_out, int out_size) {
    const float* M = (const float*)d_in[0];
    float* out = (float*)d_out;

    const int smem_bytes = (ROWS_SM * N_ + N_ + 64 + 64) * (int)sizeof(float); // 229,888 B
    static bool attr_set = false;
    if (!attr_set) {
        cudaFuncSetAttribute(rt_kernel, cudaFuncAttributeMaxDynamicSharedMemorySize, smem_bytes);
        attr_set = true;
    }

    rt_init<<<1, 32>>>();
    rt_kernel<<<GRID_, 1024, smem_bytes>>>(M, out);
}